// round 13
// baseline (speedup 1.0000x reference)
#include <cuda_runtime.h>
#include <cuda_fp16.h>
#include <math.h>

#define NN 100000
#define EE 1200000
#define HH 64
#define GG 1000
#define CC 10
#define BN_EPS 1e-5f
#define SCAN_BLOCKS 98   // 98*1024 >= 100000

// ---------------- scratch (statically zero-initialized; self-cleaning) -------
__device__ int     g_indeg[NN];        // zeroed by scan_final for next call
__device__ int     g_rowstart[NN + 1];
__device__ int     g_epos[EE];
__device__ int     g_srcsorted[EE];
__device__ int     g_bsum[SCAN_BLOCKS];
__device__ float   g_dis[NN];
__device__ __half2 g_bufH[NN * 32];    // xw (layer0: raw; layers1-2: *dis), fp16
__device__ __half2 g_bufC2[NN * 32];   // agg (pre-BN activation), fp16
__device__ float   g_stats[3 * 2048];  // per-layer: 8 replicas x (128 sum + 128 sumsq); self-cleaned
__device__ float   g_gsum[GG * HH];    // zeroed by head for next call
__device__ float   g_gcnt[GG];         // zeroed by head for next call

// ---------------- degree + per-edge slot (4 edges/thread) --------------------
__global__ void deg_pos_kernel(const int* __restrict__ dst) {
    int t = blockIdx.x * blockDim.x + threadIdx.x;
    int e = t * 4;
    if (e + 3 < EE) {
        int4 d = *(const int4*)&dst[e];
        int p0 = atomicAdd(&g_indeg[d.x], 1);
        int p1 = atomicAdd(&g_indeg[d.y], 1);
        int p2 = atomicAdd(&g_indeg[d.z], 1);
        int p3 = atomicAdd(&g_indeg[d.w], 1);
        *(int4*)&g_epos[e] = make_int4(p0, p1, p2, p3);
    } else {
        for (; e < EE; e++)
            g_epos[e] = atomicAdd(&g_indeg[dst[e]], 1);
    }
}

// ---------------- scan stage 1: per-block sums + dis --------------------------
__global__ __launch_bounds__(1024) void scan_part_kernel() {
    __shared__ int wsum[32];
    const int tid = threadIdx.x;
    const int i = blockIdx.x * 1024 + tid;
    int v = (i < NN) ? g_indeg[i] : 0;
    if (i < NN) g_dis[i] = rsqrtf((float)v + 1.0f);
    int s = v;
    #pragma unroll
    for (int off = 16; off > 0; off >>= 1) s += __shfl_down_sync(0xffffffffu, s, off);
    if ((tid & 31) == 0) wsum[tid >> 5] = s;
    __syncthreads();
    if (tid < 32) {
        int t = wsum[tid];
        #pragma unroll
        for (int off = 16; off > 0; off >>= 1) t += __shfl_down_sync(0xffffffffu, t, off);
        if (tid == 0) g_bsum[blockIdx.x] = t;
    }
}

// ---------------- scan stage 2: rowstart with inline lookback ----------------
// (also zeroes indeg for next graph replay)
__global__ __launch_bounds__(1024) void scan_final_kernel() {
    __shared__ int warpsum[32];
    __shared__ int warpincl[32];
    __shared__ int lbw[4];
    __shared__ int s_off;
    const int tid = threadIdx.x;
    const int lane = tid & 31;
    const int w = tid >> 5;
    const int i = blockIdx.x * 1024 + tid;
    int v = (i < NN) ? g_indeg[i] : 0;

    int x = v;
    #pragma unroll
    for (int off = 1; off < 32; off <<= 1) {
        int t = __shfl_up_sync(0xffffffffu, x, off);
        if (lane >= off) x += t;
    }
    if (lane == 31) warpsum[w] = x;

    if (tid < 128) {
        int lb = (tid < blockIdx.x) ? g_bsum[tid] : 0;
        #pragma unroll
        for (int off = 16; off > 0; off >>= 1) lb += __shfl_down_sync(0xffffffffu, lb, off);
        if (lane == 0) lbw[w] = lb;
    }
    __syncthreads();
    if (w == 0) {
        int y = warpsum[lane];
        #pragma unroll
        for (int off = 1; off < 32; off <<= 1) {
            int t = __shfl_up_sync(0xffffffffu, y, off);
            if (lane >= off) y += t;
        }
        warpincl[lane] = y;
        if (lane == 0) s_off = lbw[0] + lbw[1] + lbw[2] + lbw[3];
    }
    __syncthreads();
    int excl = s_off + (w ? warpincl[w - 1] : 0) + (x - v);
    if (i < NN) {
        g_rowstart[i] = excl;
        g_indeg[i] = 0;            // self-clean for next graph replay
    }
    if (i == 0 && blockIdx.x == 0) g_rowstart[NN] = EE;
}

// ---------------- CSR fill (no atomics, 4 edges/thread) ----------------------
__global__ void fill_kernel(const int* __restrict__ src, const int* __restrict__ dst) {
    int t = blockIdx.x * blockDim.x + threadIdx.x;
    int e = t * 4;
    if (e + 3 < EE) {
        int4 d = *(const int4*)&dst[e];
        int4 p = *(const int4*)&g_epos[e];
        int4 s = *(const int4*)&src[e];
        int r0 = __ldg(&g_rowstart[d.x]);
        int r1 = __ldg(&g_rowstart[d.y]);
        int r2 = __ldg(&g_rowstart[d.z]);
        int r3 = __ldg(&g_rowstart[d.w]);
        g_srcsorted[r0 + p.x] = s.x;
        g_srcsorted[r1 + p.y] = s.y;
        g_srcsorted[r2 + p.z] = s.z;
        g_srcsorted[r3 + p.w] = s.w;
    } else {
        for (; e < EE; e++)
            g_srcsorted[g_rowstart[dst[e]] + g_epos[e]] = src[e];
    }
}

// ---------------- tensor-core GEMM (smem-staged A) ---------------------------
// bufH = half( ((bn?relu(C*sc+sh):X) @ W) * (scale_dis? dis[row] : 1) )
#define XS_STRIDE 72
__global__ __launch_bounds__(256) void gemm_tc(const float* __restrict__ Xext,
                                               const float* __restrict__ W,
                                               const float* __restrict__ gamma,
                                               const float* __restrict__ beta,
                                               int stats_l, int apply_bn,
                                               int scale_dis) {
    __shared__ __half Xs[128 * XS_STRIDE];
    __shared__ __half Ws[64 * XS_STRIDE];   // transposed: Ws[n*72 + k] = W[k][n]
    __shared__ __align__(16) float s_sc[64];
    __shared__ __align__(16) float s_sh[64];
    const int tid = threadIdx.x;
    const int wid = tid >> 5;
    const int lane = tid & 31;
    const int gid = lane >> 2;      // 0..7
    const int tig = lane & 3;       // 0..3

    // ---- load W transposed ----
    #pragma unroll
    for (int i = 0; i < 16; i++) {
        int idx = tid + i * 256;            // 0..4095
        int k = idx >> 6, n = idx & 63;
        Ws[n * XS_STRIDE + k] = __float2half(W[idx]);
    }

    // ---- BN scale/shift from stats replicas ----
    if (apply_bn) {
        if (tid < 64) {
            const float* st = g_stats + stats_l * 2048;
            float s = 0.0f, q = 0.0f;
            #pragma unroll
            for (int r = 0; r < 8; r++) {
                s += st[r * 256 + tid];
                q += st[r * 256 + 128 + tid];
            }
            float mean = s * (1.0f / NN);
            float var = q * (1.0f / NN) - mean * mean;
            float scv = gamma[tid] * rsqrtf(var + BN_EPS);
            s_sc[tid] = scv;
            s_sh[tid] = beta[tid] - mean * scv;
        }
        __syncthreads();
    }

    // ---- load X tile (BN+relu fused), convert fp16 ----
    const int cq = tid & 15;                // column quad (4 floats)
    float4 sc = make_float4(1.f, 1.f, 1.f, 1.f);
    float4 sh = make_float4(0.f, 0.f, 0.f, 0.f);
    if (apply_bn) {
        sc = ((const float4*)s_sc)[cq];
        sh = ((const float4*)s_sh)[cq];
    }
    const int rowBase = blockIdx.x * 128;
    #pragma unroll
    for (int i = 0; i < 8; i++) {
        int row = (tid >> 4) + i * 16;
        int gr = rowBase + row;
        float4 v = make_float4(0.f, 0.f, 0.f, 0.f);
        if (gr < NN) {
            if (apply_bn) {
                uint2 r = ((const uint2*)g_bufC2)[(size_t)gr * 16 + cq];
                float2 f0 = __half22float2(*reinterpret_cast<__half2*>(&r.x));
                float2 f1 = __half22float2(*reinterpret_cast<__half2*>(&r.y));
                v.x = fmaxf(f0.x * sc.x + sh.x, 0.0f);
                v.y = fmaxf(f0.y * sc.y + sh.y, 0.0f);
                v.z = fmaxf(f1.x * sc.z + sh.z, 0.0f);
                v.w = fmaxf(f1.y * sc.w + sh.w, 0.0f);
            } else {
                v = ((const float4*)Xext)[(size_t)gr * 16 + cq];
            }
        }
        __half2* xp = (__half2*)&Xs[row * XS_STRIDE + cq * 4];
        xp[0] = __floats2half2_rn(v.x, v.y);
        xp[1] = __floats2half2_rn(v.z, v.w);
    }
    __syncthreads();

    // ---- mma mainloop: warp rows r0..r0+15, all 64 cols ----
    const int r0 = wid * 16;
    float acc[8][4];
    #pragma unroll
    for (int nt = 0; nt < 8; nt++)
        #pragma unroll
        for (int j = 0; j < 4; j++) acc[nt][j] = 0.0f;

    #pragma unroll
    for (int kc = 0; kc < 4; kc++) {
        const int kb = kc * 16;
        unsigned a0 = *(const unsigned*)&Xs[(r0 + gid) * XS_STRIDE + kb + tig * 2];
        unsigned a1 = *(const unsigned*)&Xs[(r0 + gid + 8) * XS_STRIDE + kb + tig * 2];
        unsigned a2 = *(const unsigned*)&Xs[(r0 + gid) * XS_STRIDE + kb + 8 + tig * 2];
        unsigned a3 = *(const unsigned*)&Xs[(r0 + gid + 8) * XS_STRIDE + kb + 8 + tig * 2];
        #pragma unroll
        for (int nt = 0; nt < 8; nt++) {
            unsigned b0 = *(const unsigned*)&Ws[(nt * 8 + gid) * XS_STRIDE + kb + tig * 2];
            unsigned b1 = *(const unsigned*)&Ws[(nt * 8 + gid) * XS_STRIDE + kb + 8 + tig * 2];
            asm volatile(
                "mma.sync.aligned.m16n8k16.row.col.f32.f16.f16.f32 "
                "{%0,%1,%2,%3}, {%4,%5,%6,%7}, {%8,%9}, {%0,%1,%2,%3};"
                : "+f"(acc[nt][0]), "+f"(acc[nt][1]), "+f"(acc[nt][2]), "+f"(acc[nt][3])
                : "r"(a0), "r"(a1), "r"(a2), "r"(a3), "r"(b0), "r"(b1));
        }
    }

    // ---- epilogue: optional dis scale, write fp16 ----
    __half2* BH = (__half2*)g_bufH;
    const int rA = rowBase + r0 + gid;
    const int rB = rA + 8;
    const bool vA = rA < NN, vB = rB < NN;
    float dA = 1.0f, dB = 1.0f;
    if (scale_dis) {
        dA = vA ? g_dis[rA] : 0.0f;
        dB = vB ? g_dis[rB] : 0.0f;
    }
    #pragma unroll
    for (int nt = 0; nt < 8; nt++) {
        if (vA) BH[(size_t)rA * 32 + nt * 4 + tig] = __floats2half2_rn(acc[nt][0] * dA, acc[nt][1] * dA);
        if (vB) BH[(size_t)rB * 32 + nt * 4 + tig] = __floats2half2_rn(acc[nt][2] * dB, acc[nt][3] * dB);
    }
}

// ---------------- gather + bias + BN stats -----------------------------------
// pre_scaled=1: rows already *dis (layers 1-2). pre_scaled=0: multiply per-edge
// dis[s] and self by dis[node] (layer 0; lets gemm0 run with no deps).
__global__ __launch_bounds__(256) void gather_stats(const float* __restrict__ bias,
                                                    int stats_l, int clear_l,
                                                    int pre_scaled) {
    __shared__ float4 s_v[256];
    __shared__ float4 s_q[256];
    const int tid = threadIdx.x;
    const int node = blockIdx.x * 16 + (tid >> 4);
    const int sub = tid & 15;
    const uint2* Bh = (const uint2*)g_bufH;

    if (clear_l >= 0 && blockIdx.x < 8)
        g_stats[clear_l * 2048 + blockIdx.x * 256 + tid] = 0.0f;

    const float dd = g_dis[node];
    float4 acc;
    {
        uint2 r = __ldg(&Bh[(size_t)node * 16 + sub]);   // self term
        float2 f0 = __half22float2(*reinterpret_cast<__half2*>(&r.x));
        float2 f1 = __half22float2(*reinterpret_cast<__half2*>(&r.y));
        float sf = pre_scaled ? 1.0f : dd;
        acc.x = f0.x * sf; acc.y = f0.y * sf; acc.z = f1.x * sf; acc.w = f1.y * sf;
    }

    int e = g_rowstart[node];
    const int end = g_rowstart[node + 1];
    if (pre_scaled) {
        for (; e + 4 <= end; e += 4) {
            int s0 = __ldg(&g_srcsorted[e]);
            int s1 = __ldg(&g_srcsorted[e + 1]);
            int s2 = __ldg(&g_srcsorted[e + 2]);
            int s3 = __ldg(&g_srcsorted[e + 3]);
            uint2 r0 = __ldg(&Bh[(size_t)s0 * 16 + sub]);
            uint2 r1 = __ldg(&Bh[(size_t)s1 * 16 + sub]);
            uint2 r2 = __ldg(&Bh[(size_t)s2 * 16 + sub]);
            uint2 r3 = __ldg(&Bh[(size_t)s3 * 16 + sub]);
            float2 a0 = __half22float2(*reinterpret_cast<__half2*>(&r0.x));
            float2 b0 = __half22float2(*reinterpret_cast<__half2*>(&r0.y));
            float2 a1 = __half22float2(*reinterpret_cast<__half2*>(&r1.x));
            float2 b1 = __half22float2(*reinterpret_cast<__half2*>(&r1.y));
            float2 a2 = __half22float2(*reinterpret_cast<__half2*>(&r2.x));
            float2 b2 = __half22float2(*reinterpret_cast<__half2*>(&r2.y));
            float2 a3 = __half22float2(*reinterpret_cast<__half2*>(&r3.x));
            float2 b3 = __half22float2(*reinterpret_cast<__half2*>(&r3.y));
            acc.x += a0.x + a1.x + a2.x + a3.x;
            acc.y += a0.y + a1.y + a2.y + a3.y;
            acc.z += b0.x + b1.x + b2.x + b3.x;
            acc.w += b0.y + b1.y + b2.y + b3.y;
        }
        for (; e < end; e++) {
            int s0 = __ldg(&g_srcsorted[e]);
            uint2 r0 = __ldg(&Bh[(size_t)s0 * 16 + sub]);
            float2 a0 = __half22float2(*reinterpret_cast<__half2*>(&r0.x));
            float2 b0 = __half22float2(*reinterpret_cast<__half2*>(&r0.y));
            acc.x += a0.x; acc.y += a0.y; acc.z += b0.x; acc.w += b0.y;
        }
    } else {
        for (; e + 4 <= end; e += 4) {
            int s0 = __ldg(&g_srcsorted[e]);
            int s1 = __ldg(&g_srcsorted[e + 1]);
            int s2 = __ldg(&g_srcsorted[e + 2]);
            int s3 = __ldg(&g_srcsorted[e + 3]);
            float n0 = __ldg(&g_dis[s0]);
            float n1 = __ldg(&g_dis[s1]);
            float n2 = __ldg(&g_dis[s2]);
            float n3 = __ldg(&g_dis[s3]);
            uint2 r0 = __ldg(&Bh[(size_t)s0 * 16 + sub]);
            uint2 r1 = __ldg(&Bh[(size_t)s1 * 16 + sub]);
            uint2 r2 = __ldg(&Bh[(size_t)s2 * 16 + sub]);
            uint2 r3 = __ldg(&Bh[(size_t)s3 * 16 + sub]);
            float2 a0 = __half22float2(*reinterpret_cast<__half2*>(&r0.x));
            float2 b0 = __half22float2(*reinterpret_cast<__half2*>(&r0.y));
            float2 a1 = __half22float2(*reinterpret_cast<__half2*>(&r1.x));
            float2 b1 = __half22float2(*reinterpret_cast<__half2*>(&r1.y));
            float2 a2 = __half22float2(*reinterpret_cast<__half2*>(&r2.x));
            float2 b2 = __half22float2(*reinterpret_cast<__half2*>(&r2.y));
            float2 a3 = __half22float2(*reinterpret_cast<__half2*>(&r3.x));
            float2 b3 = __half22float2(*reinterpret_cast<__half2*>(&r3.y));
            acc.x += a0.x * n0 + a1.x * n1 + a2.x * n2 + a3.x * n3;
            acc.y += a0.y * n0 + a1.y * n1 + a2.y * n2 + a3.y * n3;
            acc.z += b0.x * n0 + b1.x * n1 + b2.x * n2 + b3.x * n3;
            acc.w += b0.y * n0 + b1.y * n1 + b2.y * n2 + b3.y * n3;
        }
        for (; e < end; e++) {
            int s0 = __ldg(&g_srcsorted[e]);
            float n0 = __ldg(&g_dis[s0]);
            uint2 r0 = __ldg(&Bh[(size_t)s0 * 16 + sub]);
            float2 a0 = __half22float2(*reinterpret_cast<__half2*>(&r0.x));
            float2 b0 = __half22float2(*reinterpret_cast<__half2*>(&r0.y));
            acc.x += a0.x * n0; acc.y += a0.y * n0; acc.z += b0.x * n0; acc.w += b0.y * n0;
        }
    }

    const float4 bb = ((const float4*)bias)[sub];
    float4 o;
    o.x = acc.x * dd + bb.x;
    o.y = acc.y * dd + bb.y;
    o.z = acc.z * dd + bb.z;
    o.w = acc.w * dd + bb.w;
    {
        uint2 pk;
        __half2 h0 = __floats2half2_rn(o.x, o.y);
        __half2 h1 = __floats2half2_rn(o.z, o.w);
        pk.x = *reinterpret_cast<unsigned*>(&h0);
        pk.y = *reinterpret_cast<unsigned*>(&h1);
        ((uint2*)g_bufC2)[(size_t)node * 16 + sub] = pk;
    }

    float4 q;
    q.x = o.x * o.x; q.y = o.y * o.y; q.z = o.z * o.z; q.w = o.w * o.w;
    s_v[tid] = o;
    s_q[tid] = q;
    __syncthreads();
    #pragma unroll
    for (int st = 128; st >= 16; st >>= 1) {
        if (tid < st) {
            float4 a = s_v[tid], b2 = s_v[tid + st];
            a.x += b2.x; a.y += b2.y; a.z += b2.z; a.w += b2.w;
            s_v[tid] = a;
            float4 c2 = s_q[tid], d2 = s_q[tid + st];
            c2.x += d2.x; c2.y += d2.y; c2.z += d2.z; c2.w += d2.w;
            s_q[tid] = c2;
        }
        __syncthreads();
    }
    if (tid < 16) {
        float* rep = g_stats + stats_l * 2048 + (blockIdx.x & 7) * 256;
        atomicAdd(&((float4*)rep)[tid], s_v[tid]);
        atomicAdd(&((float4*)(rep + 128))[tid], s_q[tid]);
    }
}

// ---------------- pool (final BN per block, applies, pools) ------------------
__global__ __launch_bounds__(256) void pool_fused_kernel(const int* __restrict__ batch,
                                                         const float* __restrict__ gamma,
                                                         const float* __restrict__ beta) {
    __shared__ __align__(16) float s_sc[64];
    __shared__ __align__(16) float s_sh[64];
    const int tid = threadIdx.x;
    if (tid < 64) {
        const float* st = g_stats + 2 * 2048;
        float s = 0.0f, q = 0.0f;
        #pragma unroll
        for (int r = 0; r < 8; r++) {
            s += st[r * 256 + tid];
            q += st[r * 256 + 128 + tid];
        }
        float mean = s * (1.0f / NN);
        float var = q * (1.0f / NN) - mean * mean;
        float scv = gamma[tid] * rsqrtf(var + BN_EPS);
        s_sc[tid] = scv;
        s_sh[tid] = beta[tid] - mean * scv;
    }
    __syncthreads();

    int i = blockIdx.x * blockDim.x + tid;
    if (i >= NN * 16) return;
    int r = i >> 4;
    int sub = i & 15;
    int g = __ldg(&batch[r]);
    uint2 rc = ((const uint2*)g_bufC2)[i];
    float2 f0 = __half22float2(*reinterpret_cast<__half2*>(&rc.x));
    float2 f1 = __half22float2(*reinterpret_cast<__half2*>(&rc.y));
    float4 sc = ((const float4*)s_sc)[sub];
    float4 sh = ((const float4*)s_sh)[sub];
    float4 o;
    o.x = fmaxf(f0.x * sc.x + sh.x, 0.0f);
    o.y = fmaxf(f0.y * sc.y + sh.y, 0.0f);
    o.z = fmaxf(f1.x * sc.z + sh.z, 0.0f);
    o.w = fmaxf(f1.y * sc.w + sh.w, 0.0f);
    atomicAdd(((float4*)(g_gsum + (size_t)g * 64)) + sub, o);
    if (sub == 0) atomicAdd(&g_gcnt[g], 1.0f);
}

// ---------------- head (+ self-clean gsum/gcnt/stats[2]) ---------------------
__global__ void head_kernel(const float* __restrict__ fc1w, const float* __restrict__ fc1b,
                            const float* __restrict__ fc2w, const float* __restrict__ fc2b,
                            float* __restrict__ out) {
    int g = blockIdx.x;
    int j = threadIdx.x;  // 0..31
    __shared__ float pooled[64];
    __shared__ float z1[32];
    __shared__ float z2[CC];
    float cnt = fmaxf(g_gcnt[g], 1.0f);
    float inv = 1.0f / cnt;
    pooled[j]      = g_gsum[(size_t)g * 64 + j] * inv;
    pooled[j + 32] = g_gsum[(size_t)g * 64 + j + 32] * inv;
    __syncwarp();
    g_gsum[(size_t)g * 64 + j] = 0.0f;
    g_gsum[(size_t)g * 64 + j + 32] = 0.0f;
    if (j == 0) g_gcnt[g] = 0.0f;
    if (g < 64) g_stats[2 * 2048 + g * 32 + j] = 0.0f;

    float a = fc1b[j];
    #pragma unroll
    for (int k = 0; k < 64; k++) a += pooled[k] * fc1w[k * 32 + j];
    z1[j] = fmaxf(a, 0.0f);
    __syncwarp();
    if (j < CC) {
        float b = fc2b[j];
        #pragma unroll
        for (int k = 0; k < 32; k++) b += z1[k] * fc2w[k * CC + j];
        z2[j] = b;
    }
    __syncwarp();
    if (j < CC) {
        float m = -1e30f;
        #pragma unroll
        for (int c = 0; c < CC; c++) m = fmaxf(m, z2[c]);
        float se = 0.0f;
        #pragma unroll
        for (int c = 0; c < CC; c++) se += expf(z2[c] - m);
        out[(size_t)g * CC + j] = z2[j] - m - logf(se);
    }
}

// ---------------- launch -------------------------------------------------------
extern "C" void kernel_launch(void* const* d_in, const int* in_sizes, int n_in,
                              void* d_out, int out_size) {
    const float* x      = (const float*)d_in[0];
    const int*   ei     = (const int*)d_in[1];
    const int*   batch  = (const int*)d_in[2];
    const float* W[3]   = {(const float*)d_in[3], (const float*)d_in[7], (const float*)d_in[11]};
    const float* b[3]   = {(const float*)d_in[4], (const float*)d_in[8], (const float*)d_in[12]};
    const float* gm[3]  = {(const float*)d_in[5], (const float*)d_in[9], (const float*)d_in[13]};
    const float* be[3]  = {(const float*)d_in[6], (const float*)d_in[10], (const float*)d_in[14]};
    const float* fc1w   = (const float*)d_in[15];
    const float* fc1b   = (const float*)d_in[16];
    const float* fc2w   = (const float*)d_in[17];
    const float* fc2b   = (const float*)d_in[18];
    float* out = (float*)d_out;

    const int* src = ei;
    const int* dst = ei + EE;

    const int gemm_grid = (NN + 127) / 128;   // 782

    // one-time side stream + events (host handles only; no device allocation)
    static cudaStream_t s1 = nullptr;
    static cudaEvent_t evFork = nullptr, evJoin = nullptr;
    if (s1 == nullptr) {
        cudaStreamCreateWithFlags(&s1, cudaStreamNonBlocking);
        cudaEventCreateWithFlags(&evFork, cudaEventDisableTiming);
        cudaEventCreateWithFlags(&evJoin, cudaEventDisableTiming);
    }

    // fork at t=0: gemm0 has NO dependencies (raw xw, no dis scaling)
    cudaEventRecord(evFork, 0);
    cudaStreamWaitEvent(s1, evFork, 0);
    gemm_tc<<<gemm_grid, 256, 0, s1>>>(x, W[0], gm[0], be[0], 0, 0, /*scale_dis=*/0);
    cudaEventRecord(evJoin, s1);

    // main stream: full CSR build, overlapped with gemm0
    deg_pos_kernel<<<(EE / 4 + 255) / 256, 256>>>(dst);
    scan_part_kernel<<<SCAN_BLOCKS, 1024>>>();            // computes dis
    scan_final_kernel<<<SCAN_BLOCKS, 1024>>>();           // inline lookback
    fill_kernel<<<(EE / 4 + 255) / 256, 256>>>(src, dst);

    // join: gather0 needs CSR + dis (main) and bufH (s1)
    cudaStreamWaitEvent(0, evJoin, 0);

    for (int l = 0; l < 3; l++) {
        if (l > 0)
            gemm_tc<<<gemm_grid, 256>>>(x, W[l], gm[l - 1], be[l - 1], l - 1, 1, /*scale_dis=*/1);
        gather_stats<<<NN / 16, 256>>>(b[l], l, l - 1, /*pre_scaled=*/l > 0);
    }

    pool_fused_kernel<<<(NN * 16 + 255) / 256, 256>>>(batch, gm[2], be[2]);
    head_kernel<<<GG, 32>>>(fc1w, fc1b, fc2w, fc2b, out);
}

// round 14
// speedup vs baseline: 1.0481x; 1.0481x over previous
#include <cuda_runtime.h>
#include <cuda_fp16.h>
#include <math.h>

#define NN 100000
#define EE 1200000
#define HH 64
#define GG 1000
#define CC 10
#define BN_EPS 1e-5f
#define SCAN_BLOCKS 98   // 98*1024 >= 100000

// ---------------- scratch (statically zero-initialized; self-cleaning) -------
__device__ int     g_indeg[NN];        // zeroed by scan_fused for next call
__device__ int     g_rowstart[NN + 1];
__device__ int     g_epos[EE];
__device__ int     g_srcsorted[EE];
__device__ int     g_bsum1[SCAN_BLOCKS];  // blocksum+1 (0 = not ready); zeroed by fill
__device__ float   g_dis[NN];
__device__ __half2 g_bufH[NN * 32];    // xw*dis in fp16 (64 halves per row)
__device__ __half2 g_bufC2[NN * 32];   // agg (pre-BN activation), fp16
__device__ float   g_stats[3 * 2048];  // per-layer: 8 replicas x (128 sum + 128 sumsq); self-cleaned
__device__ float   g_gsum[GG * HH];    // zeroed by head for next call
__device__ float   g_gcnt[GG];         // zeroed by head for next call

// ---------------- degree + per-edge slot (4 edges/thread) --------------------
__global__ void deg_pos_kernel(const int* __restrict__ dst) {
    int t = blockIdx.x * blockDim.x + threadIdx.x;
    int e = t * 4;
    if (e + 3 < EE) {
        int4 d = *(const int4*)&dst[e];
        int p0 = atomicAdd(&g_indeg[d.x], 1);
        int p1 = atomicAdd(&g_indeg[d.y], 1);
        int p2 = atomicAdd(&g_indeg[d.z], 1);
        int p3 = atomicAdd(&g_indeg[d.w], 1);
        *(int4*)&g_epos[e] = make_int4(p0, p1, p2, p3);
    } else {
        for (; e < EE; e++)
            g_epos[e] = atomicAdd(&g_indeg[dst[e]], 1);
    }
}

// ---------------- fused single-pass scan --------------------------------------
// Computes dis, rowstart (exclusive scan of indeg), zeroes indeg.
// Block aggregates published via g_bsum1[bid]=sum+1 (nonzero = ready);
// 98 blocks all wave-1 resident -> spin is deadlock-free.
__global__ __launch_bounds__(1024) void scan_fused_kernel() {
    __shared__ int warpsum[32];
    __shared__ int warpincl[32];
    __shared__ int lbw[4];
    __shared__ int s_off;
    const int tid = threadIdx.x;
    const int lane = tid & 31;
    const int w = tid >> 5;
    const int i = blockIdx.x * 1024 + tid;
    int v = (i < NN) ? g_indeg[i] : 0;
    if (i < NN) g_dis[i] = rsqrtf((float)v + 1.0f);

    // intra-block inclusive warp scan
    int x = v;
    #pragma unroll
    for (int off = 1; off < 32; off <<= 1) {
        int t = __shfl_up_sync(0xffffffffu, x, off);
        if (lane >= off) x += t;
    }
    if (lane == 31) warpsum[w] = x;
    __syncthreads();
    if (w == 0) {
        int y = warpsum[lane];
        #pragma unroll
        for (int off = 1; off < 32; off <<= 1) {
            int t = __shfl_up_sync(0xffffffffu, y, off);
            if (lane >= off) y += t;
        }
        warpincl[lane] = y;
        if (lane == 31) {
            // publish block aggregate (+1 so nonzero = ready)
            *(volatile int*)&g_bsum1[blockIdx.x] = y + 1;
        }
    }

    // lookback: spin-read predecessor aggregates (tid<128 covers 98 blocks)
    if (tid < 128) {
        int lb = 0;
        if (tid < blockIdx.x) {
            int val;
            do { val = *(volatile int*)&g_bsum1[tid]; } while (val == 0);
            lb = val - 1;
        }
        #pragma unroll
        for (int off = 16; off > 0; off >>= 1) lb += __shfl_down_sync(0xffffffffu, lb, off);
        if (lane == 0) lbw[w] = lb;
    }
    __syncthreads();
    if (tid == 0) s_off = lbw[0] + lbw[1] + lbw[2] + lbw[3];
    __syncthreads();

    int excl = s_off + (w ? warpincl[w - 1] : 0) + (x - v);
    if (i < NN) {
        g_rowstart[i] = excl;
        g_indeg[i] = 0;            // self-clean for next graph replay
    }
    if (i == 0 && blockIdx.x == 0) g_rowstart[NN] = EE;
}

// ---------------- CSR fill (no atomics, 4 edges/thread) ----------------------
// Also re-zeroes the scan flags for the next graph replay.
__global__ void fill_kernel(const int* __restrict__ src, const int* __restrict__ dst) {
    if (blockIdx.x == 0 && threadIdx.x < SCAN_BLOCKS)
        g_bsum1[threadIdx.x] = 0;
    int t = blockIdx.x * blockDim.x + threadIdx.x;
    int e = t * 4;
    if (e + 3 < EE) {
        int4 d = *(const int4*)&dst[e];
        int4 p = *(const int4*)&g_epos[e];
        int4 s = *(const int4*)&src[e];
        int r0 = __ldg(&g_rowstart[d.x]);
        int r1 = __ldg(&g_rowstart[d.y]);
        int r2 = __ldg(&g_rowstart[d.z]);
        int r3 = __ldg(&g_rowstart[d.w]);
        g_srcsorted[r0 + p.x] = s.x;
        g_srcsorted[r1 + p.y] = s.y;
        g_srcsorted[r2 + p.z] = s.z;
        g_srcsorted[r3 + p.w] = s.w;
    } else {
        for (; e < EE; e++)
            g_srcsorted[g_rowstart[dst[e]] + g_epos[e]] = src[e];
    }
}

// ---------------- tensor-core GEMM (smem-staged A) ---------------------------
// bufH = half( ((bn?relu(C*sc+sh):X) @ W) * dis[row] )
#define XS_STRIDE 72
__global__ __launch_bounds__(256) void gemm_tc(const float* __restrict__ Xext,
                                               const float* __restrict__ W,
                                               const float* __restrict__ gamma,
                                               const float* __restrict__ beta,
                                               int stats_l, int apply_bn) {
    __shared__ __half Xs[128 * XS_STRIDE];
    __shared__ __half Ws[64 * XS_STRIDE];   // transposed: Ws[n*72 + k] = W[k][n]
    __shared__ __align__(16) float s_sc[64];
    __shared__ __align__(16) float s_sh[64];
    const int tid = threadIdx.x;
    const int wid = tid >> 5;
    const int lane = tid & 31;
    const int gid = lane >> 2;      // 0..7
    const int tig = lane & 3;       // 0..3

    // ---- load W transposed ----
    #pragma unroll
    for (int i = 0; i < 16; i++) {
        int idx = tid + i * 256;            // 0..4095
        int k = idx >> 6, n = idx & 63;
        Ws[n * XS_STRIDE + k] = __float2half(W[idx]);
    }

    // ---- BN scale/shift from stats replicas ----
    if (apply_bn) {
        if (tid < 64) {
            const float* st = g_stats + stats_l * 2048;
            float s = 0.0f, q = 0.0f;
            #pragma unroll
            for (int r = 0; r < 8; r++) {
                s += st[r * 256 + tid];
                q += st[r * 256 + 128 + tid];
            }
            float mean = s * (1.0f / NN);
            float var = q * (1.0f / NN) - mean * mean;
            float scv = gamma[tid] * rsqrtf(var + BN_EPS);
            s_sc[tid] = scv;
            s_sh[tid] = beta[tid] - mean * scv;
        }
        __syncthreads();
    }

    // ---- load X tile (BN+relu fused), convert fp16 ----
    const int cq = tid & 15;                // column quad (4 floats)
    float4 sc = make_float4(1.f, 1.f, 1.f, 1.f);
    float4 sh = make_float4(0.f, 0.f, 0.f, 0.f);
    if (apply_bn) {
        sc = ((const float4*)s_sc)[cq];
        sh = ((const float4*)s_sh)[cq];
    }
    const int rowBase = blockIdx.x * 128;
    #pragma unroll
    for (int i = 0; i < 8; i++) {
        int row = (tid >> 4) + i * 16;
        int gr = rowBase + row;
        float4 v = make_float4(0.f, 0.f, 0.f, 0.f);
        if (gr < NN) {
            if (apply_bn) {
                uint2 r = ((const uint2*)g_bufC2)[(size_t)gr * 16 + cq];
                float2 f0 = __half22float2(*reinterpret_cast<__half2*>(&r.x));
                float2 f1 = __half22float2(*reinterpret_cast<__half2*>(&r.y));
                v.x = fmaxf(f0.x * sc.x + sh.x, 0.0f);
                v.y = fmaxf(f0.y * sc.y + sh.y, 0.0f);
                v.z = fmaxf(f1.x * sc.z + sh.z, 0.0f);
                v.w = fmaxf(f1.y * sc.w + sh.w, 0.0f);
            } else {
                v = ((const float4*)Xext)[(size_t)gr * 16 + cq];
            }
        }
        __half2* xp = (__half2*)&Xs[row * XS_STRIDE + cq * 4];
        xp[0] = __floats2half2_rn(v.x, v.y);
        xp[1] = __floats2half2_rn(v.z, v.w);
    }
    __syncthreads();

    // ---- mma mainloop: warp rows r0..r0+15, all 64 cols ----
    const int r0 = wid * 16;
    float acc[8][4];
    #pragma unroll
    for (int nt = 0; nt < 8; nt++)
        #pragma unroll
        for (int j = 0; j < 4; j++) acc[nt][j] = 0.0f;

    #pragma unroll
    for (int kc = 0; kc < 4; kc++) {
        const int kb = kc * 16;
        unsigned a0 = *(const unsigned*)&Xs[(r0 + gid) * XS_STRIDE + kb + tig * 2];
        unsigned a1 = *(const unsigned*)&Xs[(r0 + gid + 8) * XS_STRIDE + kb + tig * 2];
        unsigned a2 = *(const unsigned*)&Xs[(r0 + gid) * XS_STRIDE + kb + 8 + tig * 2];
        unsigned a3 = *(const unsigned*)&Xs[(r0 + gid + 8) * XS_STRIDE + kb + 8 + tig * 2];
        #pragma unroll
        for (int nt = 0; nt < 8; nt++) {
            unsigned b0 = *(const unsigned*)&Ws[(nt * 8 + gid) * XS_STRIDE + kb + tig * 2];
            unsigned b1 = *(const unsigned*)&Ws[(nt * 8 + gid) * XS_STRIDE + kb + 8 + tig * 2];
            asm volatile(
                "mma.sync.aligned.m16n8k16.row.col.f32.f16.f16.f32 "
                "{%0,%1,%2,%3}, {%4,%5,%6,%7}, {%8,%9}, {%0,%1,%2,%3};"
                : "+f"(acc[nt][0]), "+f"(acc[nt][1]), "+f"(acc[nt][2]), "+f"(acc[nt][3])
                : "r"(a0), "r"(a1), "r"(a2), "r"(a3), "r"(b0), "r"(b1));
        }
    }

    // ---- epilogue: scale by dis[row], write fp16 ----
    __half2* BH = (__half2*)g_bufH;
    const int rA = rowBase + r0 + gid;
    const int rB = rA + 8;
    const bool vA = rA < NN, vB = rB < NN;
    const float dA = vA ? g_dis[rA] : 0.0f;
    const float dB = vB ? g_dis[rB] : 0.0f;
    #pragma unroll
    for (int nt = 0; nt < 8; nt++) {
        if (vA) BH[(size_t)rA * 32 + nt * 4 + tig] = __floats2half2_rn(acc[nt][0] * dA, acc[nt][1] * dA);
        if (vB) BH[(size_t)rB * 32 + nt * 4 + tig] = __floats2half2_rn(acc[nt][2] * dB, acc[nt][3] * dB);
    }
}

// ---------------- gather + bias + BN stats (rows pre-scaled by dis) ----------
__global__ __launch_bounds__(256) void gather_stats(const float* __restrict__ bias,
                                                    int stats_l, int clear_l) {
    __shared__ float4 s_v[256];
    __shared__ float4 s_q[256];
    const int tid = threadIdx.x;
    const int node = blockIdx.x * 16 + (tid >> 4);
    const int sub = tid & 15;
    const uint2* Bh = (const uint2*)g_bufH;

    if (clear_l >= 0 && blockIdx.x < 8)
        g_stats[clear_l * 2048 + blockIdx.x * 256 + tid] = 0.0f;

    float4 acc;
    {
        uint2 r = __ldg(&Bh[(size_t)node * 16 + sub]);   // self term (xw*dis)
        float2 f0 = __half22float2(*reinterpret_cast<__half2*>(&r.x));
        float2 f1 = __half22float2(*reinterpret_cast<__half2*>(&r.y));
        acc.x = f0.x; acc.y = f0.y; acc.z = f1.x; acc.w = f1.y;
    }

    int e = g_rowstart[node];
    const int end = g_rowstart[node + 1];
    for (; e + 4 <= end; e += 4) {
        int s0 = __ldg(&g_srcsorted[e]);
        int s1 = __ldg(&g_srcsorted[e + 1]);
        int s2 = __ldg(&g_srcsorted[e + 2]);
        int s3 = __ldg(&g_srcsorted[e + 3]);
        uint2 r0 = __ldg(&Bh[(size_t)s0 * 16 + sub]);
        uint2 r1 = __ldg(&Bh[(size_t)s1 * 16 + sub]);
        uint2 r2 = __ldg(&Bh[(size_t)s2 * 16 + sub]);
        uint2 r3 = __ldg(&Bh[(size_t)s3 * 16 + sub]);
        float2 a0 = __half22float2(*reinterpret_cast<__half2*>(&r0.x));
        float2 b0 = __half22float2(*reinterpret_cast<__half2*>(&r0.y));
        float2 a1 = __half22float2(*reinterpret_cast<__half2*>(&r1.x));
        float2 b1 = __half22float2(*reinterpret_cast<__half2*>(&r1.y));
        float2 a2 = __half22float2(*reinterpret_cast<__half2*>(&r2.x));
        float2 b2 = __half22float2(*reinterpret_cast<__half2*>(&r2.y));
        float2 a3 = __half22float2(*reinterpret_cast<__half2*>(&r3.x));
        float2 b3 = __half22float2(*reinterpret_cast<__half2*>(&r3.y));
        acc.x += a0.x + a1.x + a2.x + a3.x;
        acc.y += a0.y + a1.y + a2.y + a3.y;
        acc.z += b0.x + b1.x + b2.x + b3.x;
        acc.w += b0.y + b1.y + b2.y + b3.y;
    }
    for (; e < end; e++) {
        int s0 = __ldg(&g_srcsorted[e]);
        uint2 r0 = __ldg(&Bh[(size_t)s0 * 16 + sub]);
        float2 a0 = __half22float2(*reinterpret_cast<__half2*>(&r0.x));
        float2 b0 = __half22float2(*reinterpret_cast<__half2*>(&r0.y));
        acc.x += a0.x; acc.y += a0.y; acc.z += b0.x; acc.w += b0.y;
    }

    const float dd = g_dis[node];
    const float4 bb = ((const float4*)bias)[sub];
    float4 o;
    o.x = acc.x * dd + bb.x;
    o.y = acc.y * dd + bb.y;
    o.z = acc.z * dd + bb.z;
    o.w = acc.w * dd + bb.w;
    {
        uint2 pk;
        __half2 h0 = __floats2half2_rn(o.x, o.y);
        __half2 h1 = __floats2half2_rn(o.z, o.w);
        pk.x = *reinterpret_cast<unsigned*>(&h0);
        pk.y = *reinterpret_cast<unsigned*>(&h1);
        ((uint2*)g_bufC2)[(size_t)node * 16 + sub] = pk;
    }

    float4 q;
    q.x = o.x * o.x; q.y = o.y * o.y; q.z = o.z * o.z; q.w = o.w * o.w;
    s_v[tid] = o;
    s_q[tid] = q;
    __syncthreads();
    #pragma unroll
    for (int st = 128; st >= 16; st >>= 1) {
        if (tid < st) {
            float4 a = s_v[tid], b2 = s_v[tid + st];
            a.x += b2.x; a.y += b2.y; a.z += b2.z; a.w += b2.w;
            s_v[tid] = a;
            float4 c2 = s_q[tid], d2 = s_q[tid + st];
            c2.x += d2.x; c2.y += d2.y; c2.z += d2.z; c2.w += d2.w;
            s_q[tid] = c2;
        }
        __syncthreads();
    }
    if (tid < 16) {
        float* rep = g_stats + stats_l * 2048 + (blockIdx.x & 7) * 256;
        atomicAdd(&((float4*)rep)[tid], s_v[tid]);
        atomicAdd(&((float4*)(rep + 128))[tid], s_q[tid]);
    }
}

// ---------------- pool (final BN per block, applies, pools) ------------------
__global__ __launch_bounds__(256) void pool_fused_kernel(const int* __restrict__ batch,
                                                         const float* __restrict__ gamma,
                                                         const float* __restrict__ beta) {
    __shared__ __align__(16) float s_sc[64];
    __shared__ __align__(16) float s_sh[64];
    const int tid = threadIdx.x;
    if (tid < 64) {
        const float* st = g_stats + 2 * 2048;
        float s = 0.0f, q = 0.0f;
        #pragma unroll
        for (int r = 0; r < 8; r++) {
            s += st[r * 256 + tid];
            q += st[r * 256 + 128 + tid];
        }
        float mean = s * (1.0f / NN);
        float var = q * (1.0f / NN) - mean * mean;
        float scv = gamma[tid] * rsqrtf(var + BN_EPS);
        s_sc[tid] = scv;
        s_sh[tid] = beta[tid] - mean * scv;
    }
    __syncthreads();

    int i = blockIdx.x * blockDim.x + tid;
    if (i >= NN * 16) return;
    int r = i >> 4;
    int sub = i & 15;
    int g = __ldg(&batch[r]);
    uint2 rc = ((const uint2*)g_bufC2)[i];
    float2 f0 = __half22float2(*reinterpret_cast<__half2*>(&rc.x));
    float2 f1 = __half22float2(*reinterpret_cast<__half2*>(&rc.y));
    float4 sc = ((const float4*)s_sc)[sub];
    float4 sh = ((const float4*)s_sh)[sub];
    float4 o;
    o.x = fmaxf(f0.x * sc.x + sh.x, 0.0f);
    o.y = fmaxf(f0.y * sc.y + sh.y, 0.0f);
    o.z = fmaxf(f1.x * sc.z + sh.z, 0.0f);
    o.w = fmaxf(f1.y * sc.w + sh.w, 0.0f);
    atomicAdd(((float4*)(g_gsum + (size_t)g * 64)) + sub, o);
    if (sub == 0) atomicAdd(&g_gcnt[g], 1.0f);
}

// ---------------- head (+ self-clean gsum/gcnt/stats[2]) ---------------------
__global__ void head_kernel(const float* __restrict__ fc1w, const float* __restrict__ fc1b,
                            const float* __restrict__ fc2w, const float* __restrict__ fc2b,
                            float* __restrict__ out) {
    int g = blockIdx.x;
    int j = threadIdx.x;  // 0..31
    __shared__ float pooled[64];
    __shared__ float z1[32];
    __shared__ float z2[CC];
    float cnt = fmaxf(g_gcnt[g], 1.0f);
    float inv = 1.0f / cnt;
    pooled[j]      = g_gsum[(size_t)g * 64 + j] * inv;
    pooled[j + 32] = g_gsum[(size_t)g * 64 + j + 32] * inv;
    __syncwarp();
    g_gsum[(size_t)g * 64 + j] = 0.0f;
    g_gsum[(size_t)g * 64 + j + 32] = 0.0f;
    if (j == 0) g_gcnt[g] = 0.0f;
    if (g < 64) g_stats[2 * 2048 + g * 32 + j] = 0.0f;

    float a = fc1b[j];
    #pragma unroll
    for (int k = 0; k < 64; k++) a += pooled[k] * fc1w[k * 32 + j];
    z1[j] = fmaxf(a, 0.0f);
    __syncwarp();
    if (j < CC) {
        float b = fc2b[j];
        #pragma unroll
        for (int k = 0; k < 32; k++) b += z1[k] * fc2w[k * CC + j];
        z2[j] = b;
    }
    __syncwarp();
    if (j < CC) {
        float m = -1e30f;
        #pragma unroll
        for (int c = 0; c < CC; c++) m = fmaxf(m, z2[c]);
        float se = 0.0f;
        #pragma unroll
        for (int c = 0; c < CC; c++) se += expf(z2[c] - m);
        out[(size_t)g * CC + j] = z2[j] - m - logf(se);
    }
}

// ---------------- launch -------------------------------------------------------
extern "C" void kernel_launch(void* const* d_in, const int* in_sizes, int n_in,
                              void* d_out, int out_size) {
    const float* x      = (const float*)d_in[0];
    const int*   ei     = (const int*)d_in[1];
    const int*   batch  = (const int*)d_in[2];
    const float* W[3]   = {(const float*)d_in[3], (const float*)d_in[7], (const float*)d_in[11]};
    const float* b[3]   = {(const float*)d_in[4], (const float*)d_in[8], (const float*)d_in[12]};
    const float* gm[3]  = {(const float*)d_in[5], (const float*)d_in[9], (const float*)d_in[13]};
    const float* be[3]  = {(const float*)d_in[6], (const float*)d_in[10], (const float*)d_in[14]};
    const float* fc1w   = (const float*)d_in[15];
    const float* fc1b   = (const float*)d_in[16];
    const float* fc2w   = (const float*)d_in[17];
    const float* fc2b   = (const float*)d_in[18];
    float* out = (float*)d_out;

    const int* src = ei;
    const int* dst = ei + EE;

    const int gemm_grid = (NN + 127) / 128;   // 782

    // one-time side stream + events (host handles only; no device allocation)
    static cudaStream_t s1 = nullptr;
    static cudaEvent_t evFork = nullptr, evJoin = nullptr;
    if (s1 == nullptr) {
        cudaStreamCreateWithFlags(&s1, cudaStreamNonBlocking);
        cudaEventCreateWithFlags(&evFork, cudaEventDisableTiming);
        cudaEventCreateWithFlags(&evJoin, cudaEventDisableTiming);
    }

    deg_pos_kernel<<<(EE / 4 + 255) / 256, 256>>>(dst);
    scan_fused_kernel<<<SCAN_BLOCKS, 1024>>>();           // dis + rowstart in one pass

    // fork: gemm0 (needs only dis + x) runs concurrently with fill
    cudaEventRecord(evFork, 0);
    cudaStreamWaitEvent(s1, evFork, 0);
    gemm_tc<<<gemm_grid, 256, 0, s1>>>(x, W[0], gm[0], be[0], 0, 0);
    cudaEventRecord(evJoin, s1);

    fill_kernel<<<(EE / 4 + 255) / 256, 256>>>(src, dst);

    // join: gather0 needs both CSR (main stream) and bufH (s1)
    cudaStreamWaitEvent(0, evJoin, 0);

    for (int l = 0; l < 3; l++) {
        if (l > 0)
            gemm_tc<<<gemm_grid, 256>>>(x, W[l], gm[l - 1], be[l - 1], l - 1, 1);
        gather_stats<<<NN / 16, 256>>>(b[l], l, l - 1);
    }

    pool_fused_kernel<<<(NN * 16 + 255) / 256, 256>>>(batch, gm[2], be[2]);
    head_kernel<<<GG, 32>>>(fc1w, fc1b, fc2w, fc2b, out);
}

// round 15
// speedup vs baseline: 1.1185x; 1.0671x over previous
#include <cuda_runtime.h>
#include <cuda_fp16.h>
#include <math.h>

#define NN 100000
#define EE 1200000
#define HH 64
#define GG 1000
#define CC 10
#define BN_EPS 1e-5f
#define SCAN_BLOCKS 98   // 98*1024 >= 100000

// ---------------- scratch (statically zero-initialized; self-cleaning) -------
__device__ int            g_indeg[NN];       // zeroed by scan_fused for next call
__device__ int            g_rowstart[NN + 1];
__device__ unsigned short g_epos16[EE];      // per-edge slot (in-degree < 65536)
__device__ int            g_srcsorted[EE];
__device__ int            g_bsum1[SCAN_BLOCKS];  // blocksum+1 (0 = not ready); zeroed by fill
__device__ float          g_dis[NN];
__device__ __half2        g_bufH[NN * 32];   // xw*dis in fp16 (64 halves per row)
__device__ __half2        g_bufC2[NN * 32];  // agg (pre-BN activation), fp16
__device__ float          g_stats[3 * 2048]; // per-layer: 8 replicas x (128 sum + 128 sumsq)
__device__ float          g_gsum[GG * HH];   // zeroed by head for next call
__device__ float          g_gcnt[GG];        // zeroed by head for next call

// ---------------- degree + per-edge slot (4 edges/thread) --------------------
__global__ void deg_pos_kernel(const int* __restrict__ dst) {
    int t = blockIdx.x * blockDim.x + threadIdx.x;
    int e = t * 4;
    if (e + 3 < EE) {
        int4 d = *(const int4*)&dst[e];
        int p0 = atomicAdd(&g_indeg[d.x], 1);
        int p1 = atomicAdd(&g_indeg[d.y], 1);
        int p2 = atomicAdd(&g_indeg[d.z], 1);
        int p3 = atomicAdd(&g_indeg[d.w], 1);
        *(ushort4*)&g_epos16[e] = make_ushort4((unsigned short)p0, (unsigned short)p1,
                                               (unsigned short)p2, (unsigned short)p3);
    } else {
        for (; e < EE; e++)
            g_epos16[e] = (unsigned short)atomicAdd(&g_indeg[dst[e]], 1);
    }
}

// ---------------- fused single-pass scan --------------------------------------
__global__ __launch_bounds__(1024) void scan_fused_kernel() {
    __shared__ int warpsum[32];
    __shared__ int warpincl[32];
    __shared__ int lbw[4];
    __shared__ int s_off;
    const int tid = threadIdx.x;
    const int lane = tid & 31;
    const int w = tid >> 5;
    const int i = blockIdx.x * 1024 + tid;
    int v = (i < NN) ? g_indeg[i] : 0;
    if (i < NN) g_dis[i] = rsqrtf((float)v + 1.0f);

    int x = v;
    #pragma unroll
    for (int off = 1; off < 32; off <<= 1) {
        int t = __shfl_up_sync(0xffffffffu, x, off);
        if (lane >= off) x += t;
    }
    if (lane == 31) warpsum[w] = x;
    __syncthreads();
    if (w == 0) {
        int y = warpsum[lane];
        #pragma unroll
        for (int off = 1; off < 32; off <<= 1) {
            int t = __shfl_up_sync(0xffffffffu, y, off);
            if (lane >= off) y += t;
        }
        warpincl[lane] = y;
        if (lane == 31)
            *(volatile int*)&g_bsum1[blockIdx.x] = y + 1;   // publish aggregate
    }

    if (tid < 128) {
        int lb = 0;
        if (tid < blockIdx.x) {
            int val;
            do { val = *(volatile int*)&g_bsum1[tid]; } while (val == 0);
            lb = val - 1;
        }
        #pragma unroll
        for (int off = 16; off > 0; off >>= 1) lb += __shfl_down_sync(0xffffffffu, lb, off);
        if (lane == 0) lbw[w] = lb;
    }
    __syncthreads();
    if (tid == 0) s_off = lbw[0] + lbw[1] + lbw[2] + lbw[3];
    __syncthreads();

    int excl = s_off + (w ? warpincl[w - 1] : 0) + (x - v);
    if (i < NN) {
        g_rowstart[i] = excl;
        g_indeg[i] = 0;            // self-clean for next graph replay
    }
    if (i == 0 && blockIdx.x == 0) g_rowstart[NN] = EE;
}

// ---------------- CSR fill (no atomics, 4 edges/thread) ----------------------
__global__ void fill_kernel(const int* __restrict__ src, const int* __restrict__ dst) {
    if (blockIdx.x == 0 && threadIdx.x < SCAN_BLOCKS)
        g_bsum1[threadIdx.x] = 0;   // re-zero scan flags for next replay
    int t = blockIdx.x * blockDim.x + threadIdx.x;
    int e = t * 4;
    if (e + 3 < EE) {
        int4 d = *(const int4*)&dst[e];
        ushort4 p = *(const ushort4*)&g_epos16[e];
        int4 s = *(const int4*)&src[e];
        int r0 = __ldg(&g_rowstart[d.x]);
        int r1 = __ldg(&g_rowstart[d.y]);
        int r2 = __ldg(&g_rowstart[d.z]);
        int r3 = __ldg(&g_rowstart[d.w]);
        g_srcsorted[r0 + p.x] = s.x;
        g_srcsorted[r1 + p.y] = s.y;
        g_srcsorted[r2 + p.z] = s.z;
        g_srcsorted[r3 + p.w] = s.w;
    } else {
        for (; e < EE; e++)
            g_srcsorted[g_rowstart[dst[e]] + g_epos16[e]] = src[e];
    }
}

// ---------------- tensor-core GEMM (smem-staged A) ---------------------------
// bufH = half( ((bn?relu(C*sc+sh):X) @ W) * dis[row] )
#define XS_STRIDE 72
__global__ __launch_bounds__(256) void gemm_tc(const float* __restrict__ Xext,
                                               const float* __restrict__ W,
                                               const float* __restrict__ gamma,
                                               const float* __restrict__ beta,
                                               int stats_l, int apply_bn) {
    __shared__ __half Xs[128 * XS_STRIDE];
    __shared__ __half Ws[64 * XS_STRIDE];   // transposed: Ws[n*72 + k] = W[k][n]
    __shared__ __align__(16) float s_sc[64];
    __shared__ __align__(16) float s_sh[64];
    const int tid = threadIdx.x;
    const int wid = tid >> 5;
    const int lane = tid & 31;
    const int gid = lane >> 2;      // 0..7
    const int tig = lane & 3;       // 0..3

    #pragma unroll
    for (int i = 0; i < 16; i++) {
        int idx = tid + i * 256;            // 0..4095
        int k = idx >> 6, n = idx & 63;
        Ws[n * XS_STRIDE + k] = __float2half(W[idx]);
    }

    if (apply_bn) {
        if (tid < 64) {
            const float* st = g_stats + stats_l * 2048;
            float s = 0.0f, q = 0.0f;
            #pragma unroll
            for (int r = 0; r < 8; r++) {
                s += st[r * 256 + tid];
                q += st[r * 256 + 128 + tid];
            }
            float mean = s * (1.0f / NN);
            float var = q * (1.0f / NN) - mean * mean;
            float scv = gamma[tid] * rsqrtf(var + BN_EPS);
            s_sc[tid] = scv;
            s_sh[tid] = beta[tid] - mean * scv;
        }
        __syncthreads();
    }

    const int cq = tid & 15;                // column quad (4 floats)
    float4 sc = make_float4(1.f, 1.f, 1.f, 1.f);
    float4 sh = make_float4(0.f, 0.f, 0.f, 0.f);
    if (apply_bn) {
        sc = ((const float4*)s_sc)[cq];
        sh = ((const float4*)s_sh)[cq];
    }
    const int rowBase = blockIdx.x * 128;
    #pragma unroll
    for (int i = 0; i < 8; i++) {
        int row = (tid >> 4) + i * 16;
        int gr = rowBase + row;
        float4 v = make_float4(0.f, 0.f, 0.f, 0.f);
        if (gr < NN) {
            if (apply_bn) {
                uint2 r = ((const uint2*)g_bufC2)[(size_t)gr * 16 + cq];
                float2 f0 = __half22float2(*reinterpret_cast<__half2*>(&r.x));
                float2 f1 = __half22float2(*reinterpret_cast<__half2*>(&r.y));
                v.x = fmaxf(f0.x * sc.x + sh.x, 0.0f);
                v.y = fmaxf(f0.y * sc.y + sh.y, 0.0f);
                v.z = fmaxf(f1.x * sc.z + sh.z, 0.0f);
                v.w = fmaxf(f1.y * sc.w + sh.w, 0.0f);
            } else {
                v = ((const float4*)Xext)[(size_t)gr * 16 + cq];
            }
        }
        __half2* xp = (__half2*)&Xs[row * XS_STRIDE + cq * 4];
        xp[0] = __floats2half2_rn(v.x, v.y);
        xp[1] = __floats2half2_rn(v.z, v.w);
    }
    __syncthreads();

    const int r0 = wid * 16;
    float acc[8][4];
    #pragma unroll
    for (int nt = 0; nt < 8; nt++)
        #pragma unroll
        for (int j = 0; j < 4; j++) acc[nt][j] = 0.0f;

    #pragma unroll
    for (int kc = 0; kc < 4; kc++) {
        const int kb = kc * 16;
        unsigned a0 = *(const unsigned*)&Xs[(r0 + gid) * XS_STRIDE + kb + tig * 2];
        unsigned a1 = *(const unsigned*)&Xs[(r0 + gid + 8) * XS_STRIDE + kb + tig * 2];
        unsigned a2 = *(const unsigned*)&Xs[(r0 + gid) * XS_STRIDE + kb + 8 + tig * 2];
        unsigned a3 = *(const unsigned*)&Xs[(r0 + gid + 8) * XS_STRIDE + kb + 8 + tig * 2];
        #pragma unroll
        for (int nt = 0; nt < 8; nt++) {
            unsigned b0 = *(const unsigned*)&Ws[(nt * 8 + gid) * XS_STRIDE + kb + tig * 2];
            unsigned b1 = *(const unsigned*)&Ws[(nt * 8 + gid) * XS_STRIDE + kb + 8 + tig * 2];
            asm volatile(
                "mma.sync.aligned.m16n8k16.row.col.f32.f16.f16.f32 "
                "{%0,%1,%2,%3}, {%4,%5,%6,%7}, {%8,%9}, {%0,%1,%2,%3};"
                : "+f"(acc[nt][0]), "+f"(acc[nt][1]), "+f"(acc[nt][2]), "+f"(acc[nt][3])
                : "r"(a0), "r"(a1), "r"(a2), "r"(a3), "r"(b0), "r"(b1));
        }
    }

    __half2* BH = (__half2*)g_bufH;
    const int rA = rowBase + r0 + gid;
    const int rB = rA + 8;
    const bool vA = rA < NN, vB = rB < NN;
    const float dA = vA ? g_dis[rA] : 0.0f;
    const float dB = vB ? g_dis[rB] : 0.0f;
    #pragma unroll
    for (int nt = 0; nt < 8; nt++) {
        if (vA) BH[(size_t)rA * 32 + nt * 4 + tig] = __floats2half2_rn(acc[nt][0] * dA, acc[nt][1] * dA);
        if (vB) BH[(size_t)rB * 32 + nt * 4 + tig] = __floats2half2_rn(acc[nt][2] * dB, acc[nt][3] * dB);
    }
}

// ---------------- gather + bias + BN stats (rows pre-scaled by dis) ----------
__global__ __launch_bounds__(256) void gather_stats(const float* __restrict__ bias,
                                                    int stats_l, int clear_l) {
    __shared__ float4 s_v[256];
    __shared__ float4 s_q[256];
    const int tid = threadIdx.x;
    const int node = blockIdx.x * 16 + (tid >> 4);
    const int sub = tid & 15;
    const uint2* Bh = (const uint2*)g_bufH;

    if (clear_l >= 0 && blockIdx.x < 8)
        g_stats[clear_l * 2048 + blockIdx.x * 256 + tid] = 0.0f;

    float4 acc;
    {
        uint2 r = __ldg(&Bh[(size_t)node * 16 + sub]);   // self term (xw*dis)
        float2 f0 = __half22float2(*reinterpret_cast<__half2*>(&r.x));
        float2 f1 = __half22float2(*reinterpret_cast<__half2*>(&r.y));
        acc.x = f0.x; acc.y = f0.y; acc.z = f1.x; acc.w = f1.y;
    }

    int e = g_rowstart[node];
    const int end = g_rowstart[node + 1];
    for (; e + 4 <= end; e += 4) {
        int s0 = __ldg(&g_srcsorted[e]);
        int s1 = __ldg(&g_srcsorted[e + 1]);
        int s2 = __ldg(&g_srcsorted[e + 2]);
        int s3 = __ldg(&g_srcsorted[e + 3]);
        uint2 r0 = __ldg(&Bh[(size_t)s0 * 16 + sub]);
        uint2 r1 = __ldg(&Bh[(size_t)s1 * 16 + sub]);
        uint2 r2 = __ldg(&Bh[(size_t)s2 * 16 + sub]);
        uint2 r3 = __ldg(&Bh[(size_t)s3 * 16 + sub]);
        float2 a0 = __half22float2(*reinterpret_cast<__half2*>(&r0.x));
        float2 b0 = __half22float2(*reinterpret_cast<__half2*>(&r0.y));
        float2 a1 = __half22float2(*reinterpret_cast<__half2*>(&r1.x));
        float2 b1 = __half22float2(*reinterpret_cast<__half2*>(&r1.y));
        float2 a2 = __half22float2(*reinterpret_cast<__half2*>(&r2.x));
        float2 b2 = __half22float2(*reinterpret_cast<__half2*>(&r2.y));
        float2 a3 = __half22float2(*reinterpret_cast<__half2*>(&r3.x));
        float2 b3 = __half22float2(*reinterpret_cast<__half2*>(&r3.y));
        acc.x += a0.x + a1.x + a2.x + a3.x;
        acc.y += a0.y + a1.y + a2.y + a3.y;
        acc.z += b0.x + b1.x + b2.x + b3.x;
        acc.w += b0.y + b1.y + b2.y + b3.y;
    }
    for (; e < end; e++) {
        int s0 = __ldg(&g_srcsorted[e]);
        uint2 r0 = __ldg(&Bh[(size_t)s0 * 16 + sub]);
        float2 a0 = __half22float2(*reinterpret_cast<__half2*>(&r0.x));
        float2 b0 = __half22float2(*reinterpret_cast<__half2*>(&r0.y));
        acc.x += a0.x; acc.y += a0.y; acc.z += b0.x; acc.w += b0.y;
    }

    const float dd = g_dis[node];
    const float4 bb = ((const float4*)bias)[sub];
    float4 o;
    o.x = acc.x * dd + bb.x;
    o.y = acc.y * dd + bb.y;
    o.z = acc.z * dd + bb.z;
    o.w = acc.w * dd + bb.w;
    {
        uint2 pk;
        __half2 h0 = __floats2half2_rn(o.x, o.y);
        __half2 h1 = __floats2half2_rn(o.z, o.w);
        pk.x = *reinterpret_cast<unsigned*>(&h0);
        pk.y = *reinterpret_cast<unsigned*>(&h1);
        ((uint2*)g_bufC2)[(size_t)node * 16 + sub] = pk;
    }

    float4 q;
    q.x = o.x * o.x; q.y = o.y * o.y; q.z = o.z * o.z; q.w = o.w * o.w;
    s_v[tid] = o;
    s_q[tid] = q;
    __syncthreads();
    #pragma unroll
    for (int st = 128; st >= 16; st >>= 1) {
        if (tid < st) {
            float4 a = s_v[tid], b2 = s_v[tid + st];
            a.x += b2.x; a.y += b2.y; a.z += b2.z; a.w += b2.w;
            s_v[tid] = a;
            float4 c2 = s_q[tid], d2 = s_q[tid + st];
            c2.x += d2.x; c2.y += d2.y; c2.z += d2.z; c2.w += d2.w;
            s_q[tid] = c2;
        }
        __syncthreads();
    }
    if (tid < 16) {
        float* rep = g_stats + stats_l * 2048 + (blockIdx.x & 7) * 256;
        atomicAdd(&((float4*)rep)[tid], s_v[tid]);
        atomicAdd(&((float4*)(rep + 128))[tid], s_q[tid]);
    }
}

// ---------------- pool: BN apply + segment-reduce over sorted batch ----------
// 16 nodes per block (consecutive); run-head threads accumulate their run and
// issue one atomic per (graph-run, sub) instead of one per node.
__global__ __launch_bounds__(256) void pool_fused_kernel(const int* __restrict__ batch,
                                                         const float* __restrict__ gamma,
                                                         const float* __restrict__ beta) {
    __shared__ __align__(16) float s_sc[64];
    __shared__ __align__(16) float s_sh[64];
    __shared__ float4 s_o[256];
    __shared__ int s_g[16];
    const int tid = threadIdx.x;
    const int nloc = tid >> 4;
    const int sub = tid & 15;
    const int node = blockIdx.x * 16 + nloc;

    if (tid < 64) {
        const float* st = g_stats + 2 * 2048;
        float s = 0.0f, q = 0.0f;
        #pragma unroll
        for (int r = 0; r < 8; r++) {
            s += st[r * 256 + tid];
            q += st[r * 256 + 128 + tid];
        }
        float mean = s * (1.0f / NN);
        float var = q * (1.0f / NN) - mean * mean;
        float scv = gamma[tid] * rsqrtf(var + BN_EPS);
        s_sc[tid] = scv;
        s_sh[tid] = beta[tid] - mean * scv;
    }
    if (tid < 16) s_g[tid] = __ldg(&batch[blockIdx.x * 16 + tid]);
    __syncthreads();

    uint2 rc = ((const uint2*)g_bufC2)[(size_t)node * 16 + sub];
    float2 f0 = __half22float2(*reinterpret_cast<__half2*>(&rc.x));
    float2 f1 = __half22float2(*reinterpret_cast<__half2*>(&rc.y));
    float4 sc = ((const float4*)s_sc)[sub];
    float4 sh = ((const float4*)s_sh)[sub];
    float4 o;
    o.x = fmaxf(f0.x * sc.x + sh.x, 0.0f);
    o.y = fmaxf(f0.y * sc.y + sh.y, 0.0f);
    o.z = fmaxf(f1.x * sc.z + sh.z, 0.0f);
    o.w = fmaxf(f1.y * sc.w + sh.w, 0.0f);
    s_o[tid] = o;
    __syncthreads();

    const int g = s_g[nloc];
    const bool head = (nloc == 0) || (s_g[nloc - 1] != g);
    if (head) {
        float4 acc = o;
        int cnt = 1;
        for (int k = nloc + 1; k < 16 && s_g[k] == g; k++) {
            float4 v = s_o[k * 16 + sub];
            acc.x += v.x; acc.y += v.y; acc.z += v.z; acc.w += v.w;
            cnt++;
        }
        atomicAdd(((float4*)(g_gsum + (size_t)g * 64)) + sub, acc);
        if (sub == 0) atomicAdd(&g_gcnt[g], (float)cnt);
    }
}

// ---------------- head (+ self-clean gsum/gcnt/stats[2]) ---------------------
__global__ void head_kernel(const float* __restrict__ fc1w, const float* __restrict__ fc1b,
                            const float* __restrict__ fc2w, const float* __restrict__ fc2b,
                            float* __restrict__ out) {
    int g = blockIdx.x;
    int j = threadIdx.x;  // 0..31
    __shared__ float pooled[64];
    __shared__ float z1[32];
    __shared__ float z2[CC];
    float cnt = fmaxf(g_gcnt[g], 1.0f);
    float inv = 1.0f / cnt;
    pooled[j]      = g_gsum[(size_t)g * 64 + j] * inv;
    pooled[j + 32] = g_gsum[(size_t)g * 64 + j + 32] * inv;
    __syncwarp();
    g_gsum[(size_t)g * 64 + j] = 0.0f;
    g_gsum[(size_t)g * 64 + j + 32] = 0.0f;
    if (j == 0) g_gcnt[g] = 0.0f;
    if (g < 64) g_stats[2 * 2048 + g * 32 + j] = 0.0f;

    float a = fc1b[j];
    #pragma unroll
    for (int k = 0; k < 64; k++) a += pooled[k] * fc1w[k * 32 + j];
    z1[j] = fmaxf(a, 0.0f);
    __syncwarp();
    if (j < CC) {
        float b = fc2b[j];
        #pragma unroll
        for (int k = 0; k < 32; k++) b += z1[k] * fc2w[k * CC + j];
        z2[j] = b;
    }
    __syncwarp();
    if (j < CC) {
        float m = -1e30f;
        #pragma unroll
        for (int c = 0; c < CC; c++) m = fmaxf(m, z2[c]);
        float se = 0.0f;
        #pragma unroll
        for (int c = 0; c < CC; c++) se += expf(z2[c] - m);
        out[(size_t)g * CC + j] = z2[j] - m - logf(se);
    }
}

// ---------------- launch -------------------------------------------------------
extern "C" void kernel_launch(void* const* d_in, const int* in_sizes, int n_in,
                              void* d_out, int out_size) {
    const float* x      = (const float*)d_in[0];
    const int*   ei     = (const int*)d_in[1];
    const int*   batch  = (const int*)d_in[2];
    const float* W[3]   = {(const float*)d_in[3], (const float*)d_in[7], (const float*)d_in[11]};
    const float* b[3]   = {(const float*)d_in[4], (const float*)d_in[8], (const float*)d_in[12]};
    const float* gm[3]  = {(const float*)d_in[5], (const float*)d_in[9], (const float*)d_in[13]};
    const float* be[3]  = {(const float*)d_in[6], (const float*)d_in[10], (const float*)d_in[14]};
    const float* fc1w   = (const float*)d_in[15];
    const float* fc1b   = (const float*)d_in[16];
    const float* fc2w   = (const float*)d_in[17];
    const float* fc2b   = (const float*)d_in[18];
    float* out = (float*)d_out;

    const int* src = ei;
    const int* dst = ei + EE;

    const int gemm_grid = (NN + 127) / 128;   // 782

    static cudaStream_t s1 = nullptr;
    static cudaEvent_t evFork = nullptr, evJoin = nullptr;
    if (s1 == nullptr) {
        cudaStreamCreateWithFlags(&s1, cudaStreamNonBlocking);
        cudaEventCreateWithFlags(&evFork, cudaEventDisableTiming);
        cudaEventCreateWithFlags(&evJoin, cudaEventDisableTiming);
    }

    deg_pos_kernel<<<(EE / 4 + 255) / 256, 256>>>(dst);
    scan_fused_kernel<<<SCAN_BLOCKS, 1024>>>();           // dis + rowstart in one pass

    // fork: gemm0 (needs only dis + x) runs concurrently with fill
    cudaEventRecord(evFork, 0);
    cudaStreamWaitEvent(s1, evFork, 0);
    gemm_tc<<<gemm_grid, 256, 0, s1>>>(x, W[0], gm[0], be[0], 0, 0);
    cudaEventRecord(evJoin, s1);

    fill_kernel<<<(EE / 4 + 255) / 256, 256>>>(src, dst);

    cudaStreamWaitEvent(0, evJoin, 0);

    for (int l = 0; l < 3; l++) {
        if (l > 0)
            gemm_tc<<<gemm_grid, 256>>>(x, W[l], gm[l - 1], be[l - 1], l - 1, 1);
        gather_stats<<<NN / 16, 256>>>(b[l], l, l - 1);
    }

    pool_fused_kernel<<<NN / 16, 256>>>(batch, gm[2], be[2]);
    head_kernel<<<GG, 32>>>(fc1w, fc1b, fc2w, fc2b, out);
}